// round 8
// baseline (speedup 1.0000x reference)
#include <cuda_runtime.h>
#include <cuda_bf16.h>
#include <math_constants.h>
#include <cstdint>

// Problem constants
#define BATCH   64
#define SEQL    256
#define EDIM    512
#define SDIM    1024
#define KDIM    1024   // 2*E
#define NCLASS  2

// GEMM tile config (bf16 mma.sync m16n8k16 + ldmatrix)
#define BM 128
#define BN 128
#define BK 64                      // halves per k-tile (128 bytes of bf16)
#define LDT 72                     // padded smem row stride in halves
#define TILE_HALVES (128 * LDT)
#define TILE_BYTES  (TILE_HALVES * 2)         // 18432
#define STAGE_BYTES (2 * TILE_BYTES)          // A + B = 36864
#define SMEM_BYTES  (2 * STAGE_BYTES)         // 2 stages = 73728
#define NKT (KDIM / BK)            // 16

// Scratch (static device globals)
__device__ __nv_bfloat16 g_embs[BATCH * SEQL * EDIM];
__device__ __nv_bfloat16 g_wc[SDIM * KDIM];
__device__ float g_sentpre[BATCH * SDIM];
__device__ float g_h[BATCH * 64];

__device__ __forceinline__ void atomicMaxFloat(float* addr, float val) {
    if (val >= 0.0f) atomicMax(reinterpret_cast<int*>(addr), __float_as_int(val));
    else             atomicMin(reinterpret_cast<unsigned int*>(addr), __float_as_uint(val));
}

__device__ __forceinline__ void mma_bf16(float c[4], const uint32_t a[4],
                                         uint32_t b0, uint32_t b1) {
    asm volatile(
        "mma.sync.aligned.m16n8k16.row.col.f32.bf16.bf16.f32 "
        "{%0,%1,%2,%3}, {%4,%5,%6,%7}, {%8,%9}, {%0,%1,%2,%3};"
        : "+f"(c[0]), "+f"(c[1]), "+f"(c[2]), "+f"(c[3])
        : "r"(a[0]), "r"(a[1]), "r"(a[2]), "r"(a[3]), "r"(b0), "r"(b1));
}

__device__ __forceinline__ void ldmatrix_x4(uint32_t r[4], uint32_t addr) {
    asm volatile("ldmatrix.sync.aligned.m8n8.x4.shared.b16 {%0,%1,%2,%3}, [%4];"
                 : "=r"(r[0]), "=r"(r[1]), "=r"(r[2]), "=r"(r[3]) : "r"(addr));
}

__device__ __forceinline__ void cp_async16(uint32_t saddr, const void* gptr, bool pred) {
    int sz = pred ? 16 : 0;
    asm volatile("cp.async.cg.shared.global [%0], [%1], 16, %2;"
                 :: "r"(saddr), "l"(gptr), "r"(sz));
}

__device__ __forceinline__ uint32_t pack_bf16(float lo, float hi) {
    __nv_bfloat162 p = __floats2bfloat162_rn(lo, hi);
    return *reinterpret_cast<uint32_t*>(&p);
}

// ---------------------------------------------------------------------------
// Kernel 1a: embedding gather -> bf16
// ---------------------------------------------------------------------------
__global__ void gather_kernel(const int* __restrict__ inputs,
                              const float* __restrict__ emb_table) {
    int row = blockIdx.x;
    int tok = inputs[row];
    float4 v = reinterpret_cast<const float4*>(emb_table + (size_t)tok * EDIM)[threadIdx.x];
    uint2 o;
    o.x = pack_bf16(v.x, v.y);
    o.y = pack_bf16(v.z, v.w);
    reinterpret_cast<uint2*>(g_embs + (size_t)row * EDIM)[threadIdx.x] = o;
}

// ---------------------------------------------------------------------------
// Kernel 1b: Wc -> bf16
// ---------------------------------------------------------------------------
__global__ void wc_round_kernel(const float* __restrict__ Wc) {
    int i = blockIdx.x * blockDim.x + threadIdx.x;
    float4 v = reinterpret_cast<const float4*>(Wc)[i];
    uint2 o;
    o.x = pack_bf16(v.x, v.y);
    o.y = pack_bf16(v.z, v.w);
    reinterpret_cast<uint2*>(g_wc)[i] = o;
}

// ---------------------------------------------------------------------------
// Kernel 2: init max accumulator
// ---------------------------------------------------------------------------
__global__ void init_kernel() {
    int i = blockIdx.x * blockDim.x + threadIdx.x;
    if (i < BATCH * SDIM) g_sentpre[i] = -CUDART_INF_F;
}

// ---------------------------------------------------------------------------
// Kernel 3: BF16 tensor-core conv GEMM + fused max-pool.
// Block: 256 threads = 8 warps (2m x 4n), warp tile 64x32, ldmatrix fragments.
// Grid: (8 ntiles, 2 mtiles, 64 batches). 2-stage cp.async pipeline.
// ---------------------------------------------------------------------------
__global__ __launch_bounds__(256, 2) void conv_max_kernel(const float* __restrict__ bc)
{
    extern __shared__ __nv_bfloat16 sm[];

    const int b    = blockIdx.z;
    const int m0   = blockIdx.y * BM;
    const int n0   = blockIdx.x * BN;
    const int tid  = threadIdx.x;
    const int lane = tid & 31;
    const int warp = tid >> 5;
    const int wm   = warp >> 2;        // 0..1  (m offset wm*64)
    const int wn   = warp & 3;         // 0..3  (n offset wn*32)
    const int g    = lane >> 2;        // 0..7
    const int t    = lane & 3;         // 0..3

    const __nv_bfloat16* Ag = g_embs + (size_t)b * SEQL * EDIM + (size_t)m0 * EDIM;
    const __nv_bfloat16* Bg = g_wc + (size_t)n0 * KDIM;

    const uint32_t smem_u32 = (uint32_t)__cvta_generic_to_shared(sm);

    // ldmatrix per-thread row/col offsets (bytes)
    const uint32_t lm_row = (uint32_t)(lane & 15) * (LDT * 2);  // row * 144
    const uint32_t lm_col = (uint32_t)(lane >> 4) * 16;         // 0 or 16

    // --- tile loader: stage st <- k-tile kt (8 x 16B chunks per thread) ---
    auto load_tile = [&](int kt, int st) {
        uint32_t base = smem_u32 + (uint32_t)st * STAGE_BYTES;
#pragma unroll
        for (int i = 0; i < 8; i++) {
            int c   = tid + 256 * i;            // 0..2047
            int row = (c & 1023) >> 3;          // 0..127
            int ch  = c & 7;                    // 16B chunk within 128B of k
            uint32_t daddr = base + (c < 1024 ? 0u : (uint32_t)TILE_BYTES)
                           + (uint32_t)(row * LDT * 2 + ch * 16);
            if (c < 1024) {
                bool av = (m0 + row) < (SEQL - 1);
                cp_async16(daddr, Ag + (size_t)row * EDIM + kt * BK + ch * 8, av);
            } else {
                cp_async16(daddr, Bg + (size_t)row * KDIM + kt * BK + ch * 8, true);
            }
        }
    };

    float acc[4][4][4];
#pragma unroll
    for (int mt = 0; mt < 4; mt++)
#pragma unroll
        for (int nt = 0; nt < 4; nt++)
#pragma unroll
            for (int q = 0; q < 4; q++) acc[mt][nt][q] = 0.0f;

    load_tile(0, 0);
    asm volatile("cp.async.commit_group;");

    for (int kt = 0; kt < NKT; ++kt) {
        if (kt + 1 < NKT) {
            load_tile(kt + 1, (kt + 1) & 1);
            asm volatile("cp.async.commit_group;");
            asm volatile("cp.async.wait_group 1;");
        } else {
            asm volatile("cp.async.wait_group 0;");
        }
        __syncthreads();

        const uint32_t abase = smem_u32 + (uint32_t)(kt & 1) * STAGE_BYTES;
        const uint32_t bbase = abase + TILE_BYTES;

#pragma unroll
        for (int ks = 0; ks < 4; ks++) {       // 4 ksteps of k16 per BK=64
            const uint32_t kb = (uint32_t)ks * 32 + lm_col;
            uint32_t af[4][4];
#pragma unroll
            for (int mt = 0; mt < 4; mt++)
                ldmatrix_x4(af[mt],
                    abase + (uint32_t)(wm * 64 + mt * 16) * (LDT * 2) + lm_row + kb);
            uint32_t bq[2][4];
#pragma unroll
            for (int bn = 0; bn < 2; bn++)
                ldmatrix_x4(bq[bn],
                    bbase + (uint32_t)(wn * 32 + bn * 16) * (LDT * 2) + lm_row + kb);
#pragma unroll
            for (int mt = 0; mt < 4; mt++)
#pragma unroll
                for (int nt = 0; nt < 4; nt++) {
                    const int bn = nt >> 1, sel = nt & 1;
                    mma_bf16(acc[mt][nt], af[mt], bq[bn][sel], bq[bn][sel + 2]);
                }
        }
        __syncthreads();
    }

    // --- epilogue: per-thread column max over valid rows, shuffle-reduce over g ---
    float cmax[4][2];
#pragma unroll
    for (int nt = 0; nt < 4; nt++) { cmax[nt][0] = -CUDART_INF_F; cmax[nt][1] = -CUDART_INF_F; }

#pragma unroll
    for (int mt = 0; mt < 4; mt++) {
        int r0 = m0 + wm * 64 + mt * 16 + g;
        bool v0 = r0 < (SEQL - 1);
        bool v1 = (r0 + 8) < (SEQL - 1);
#pragma unroll
        for (int nt = 0; nt < 4; nt++) {
            if (v0) {
                cmax[nt][0] = fmaxf(cmax[nt][0], acc[mt][nt][0]);
                cmax[nt][1] = fmaxf(cmax[nt][1], acc[mt][nt][1]);
            }
            if (v1) {
                cmax[nt][0] = fmaxf(cmax[nt][0], acc[mt][nt][2]);
                cmax[nt][1] = fmaxf(cmax[nt][1], acc[mt][nt][3]);
            }
        }
    }
#pragma unroll
    for (int nt = 0; nt < 4; nt++)
#pragma unroll
        for (int j = 0; j < 2; j++) {
            float v = cmax[nt][j];
            v = fmaxf(v, __shfl_xor_sync(0xffffffffu, v, 4));
            v = fmaxf(v, __shfl_xor_sync(0xffffffffu, v, 8));
            v = fmaxf(v, __shfl_xor_sync(0xffffffffu, v, 16));
            cmax[nt][j] = v;
        }
    if (g == 0) {   // lanes 0..3 (lane == t)
#pragma unroll
        for (int nt = 0; nt < 4; nt++)
#pragma unroll
            for (int j = 0; j < 2; j++) {
                int col = n0 + wn * 32 + nt * 8 + 2 * t + j;
                atomicMaxFloat(&g_sentpre[(size_t)b * SDIM + col],
                               cmax[nt][j] + __ldg(&bc[col]));
            }
    }
}

// ---------------------------------------------------------------------------
// Kernel 4a: h[b][j] = dot(sigmoid(sentpre[b]), W1[j]) + b1[j]
// ---------------------------------------------------------------------------
__global__ __launch_bounds__(256) void h_kernel(
    const float* __restrict__ W1, const float* __restrict__ b1)
{
    const int b = blockIdx.x;
    __shared__ float sent[SDIM];
    for (int i = threadIdx.x; i < SDIM; i += 256) {
        float v = g_sentpre[(size_t)b * SDIM + i];
        sent[i] = 1.0f / (1.0f + expf(-v));
    }
    __syncthreads();

    const int w    = threadIdx.x >> 5;
    const int lane = threadIdx.x & 31;
    for (int j = w; j < 50; j += 8) {
        const float4* wrow = reinterpret_cast<const float4*>(W1 + (size_t)j * SDIM);
        float sum = 0.0f;
#pragma unroll
        for (int i = lane; i < SDIM / 4; i += 32) {
            float4 v = wrow[i];
            const float* s = &sent[i * 4];
            sum = fmaf(v.x, s[0], sum);
            sum = fmaf(v.y, s[1], sum);
            sum = fmaf(v.z, s[2], sum);
            sum = fmaf(v.w, s[3], sum);
        }
#pragma unroll
        for (int o = 16; o > 0; o >>= 1) sum += __shfl_down_sync(0xffffffffu, sum, o);
        if (lane == 0) g_h[b * 64 + j] = sum + b1[j];
    }
}

// ---------------------------------------------------------------------------
// Kernel 4b: logits + log_softmax
// ---------------------------------------------------------------------------
__global__ void out_kernel(const float* __restrict__ W2, const float* __restrict__ b2,
                           float* __restrict__ out)
{
    int b = threadIdx.x;
    if (b >= BATCH) return;
    float l0 = b2[0], l1 = b2[1];
#pragma unroll
    for (int j = 0; j < 50; j++) {
        float h = g_h[b * 64 + j];
        l0 = fmaf(h, W2[j], l0);
        l1 = fmaf(h, W2[50 + j], l1);
    }
    float m   = fmaxf(l0, l1);
    float lse = m + logf(expf(l0 - m) + expf(l1 - m));
    out[b * NCLASS + 0] = l0 - lse;
    out[b * NCLASS + 1] = l1 - lse;
}

// ---------------------------------------------------------------------------
// kernel_launch
// inputs order: inputs(int32), emb_table, Wc, bc, W1, b1, W2, b2
// ---------------------------------------------------------------------------
extern "C" void kernel_launch(void* const* d_in, const int* in_sizes, int n_in,
                              void* d_out, int out_size) {
    const int*   inputs = (const int*)  d_in[0];
    const float* emb    = (const float*)d_in[1];
    const float* Wc     = (const float*)d_in[2];
    const float* bc     = (const float*)d_in[3];
    const float* W1     = (const float*)d_in[4];
    const float* b1     = (const float*)d_in[5];
    const float* W2     = (const float*)d_in[6];
    const float* b2     = (const float*)d_in[7];
    float* out = (float*)d_out;

    cudaFuncSetAttribute(conv_max_kernel,
                         cudaFuncAttributeMaxDynamicSharedMemorySize, SMEM_BYTES);

    gather_kernel<<<BATCH * SEQL, 128>>>(inputs, emb);
    wc_round_kernel<<<(SDIM * KDIM / 4) / 256, 256>>>(Wc);
    init_kernel<<<(BATCH * SDIM + 255) / 256, 256>>>();

    dim3 grid(SDIM / BN, (SEQL + BM - 1) / BM, BATCH);   // (8, 2, 64)
    conv_max_kernel<<<grid, 256, SMEM_BYTES>>>(bc);

    h_kernel<<<BATCH, 256>>>(W1, b1);
    out_kernel<<<1, 64>>>(W2, b2, out);
}